// round 8
// baseline (speedup 1.0000x reference)
#include <cuda_runtime.h>
#include <cuda_bf16.h>
#include <cstdint>

#define N_NODES 100000
#define N_EDGES 3200000
#define F_IN 128
#define F_HID 16
#define F_OUT 32
#define SCAN_B 1024
#define NB_SCAN ((N_NODES + SCAN_B - 1) / SCAN_B)   // 98

// ---------------- scratch (device globals; no allocation allowed) ----------
__device__ int   d_cnt[N_NODES];           // in-degree (targets, no self-loop)
__device__ int   d_fill[N_NODES];          // CSR fill cursors
__device__ int   d_off[N_NODES + 1];       // CSR offsets
__device__ int   d_bsum[NB_SCAN];          // per-block sums -> exclusive bases
__device__ int   d_src[N_EDGES];           // CSR: sources grouped by target
__device__ float d_dinv[N_NODES];
__device__ float d_g1[N_NODES * F_HID];    // dinv[i] * (x W1)[i]
__device__ float d_g2[N_NODES * F_OUT];    // dinv[i] * (h W2)[i]

// ---------------- kernel: zero counts ---------------------------------------
__global__ void k_zero(int n) {
    int i = blockIdx.x * blockDim.x + threadIdx.x;
    if (i < n) d_cnt[i] = 0;
}

// ---------------- kernel: in-degree count ----------------------------------
__global__ void k_count(const int* __restrict__ ei, int E) {
    int e = blockIdx.x * blockDim.x + threadIdx.x;
    if (e >= E) return;
    atomicAdd(&d_cnt[ei[E + e]], 1);       // edge_index[1][e] (target)
}

// ---------------- scan A: per-block sums (98 blocks x 1024) -----------------
__global__ void k_blocksum(int N) {
    __shared__ int ws[32];
    int t = threadIdx.x, lane = t & 31, w = t >> 5;
    int i = blockIdx.x * SCAN_B + t;
    int s = (i < N) ? d_cnt[i] : 0;
    #pragma unroll
    for (int o = 16; o; o >>= 1) s += __shfl_xor_sync(0xFFFFFFFFu, s, o);
    if (lane == 0) ws[w] = s;
    __syncthreads();
    if (t < 32) {
        int v = ws[t];
        #pragma unroll
        for (int o = 16; o; o >>= 1) v += __shfl_xor_sync(0xFFFFFFFFu, v, o);
        if (t == 0) d_bsum[blockIdx.x] = v;
    }
}

// ---------------- scan B: exclusive scan of 98 block sums (1 warp) ----------
__global__ void k_scanb(int nb, int N) {
    int lane = threadIdx.x;
    int carry = 0;
    for (int base = 0; base < nb; base += 32) {
        int idx = base + lane;
        int v = (idx < nb) ? d_bsum[idx] : 0;
        int x = v;
        #pragma unroll
        for (int o = 1; o < 32; o <<= 1) {
            int u = __shfl_up_sync(0xFFFFFFFFu, x, o);
            if (lane >= o) x += u;
        }
        if (idx < nb) d_bsum[idx] = carry + x - v;   // exclusive
        carry += __shfl_sync(0xFFFFFFFFu, x, 31);    // chunk total
    }
    if (lane == 0) d_off[N] = carry;                 // == E
}

// ---------------- scan C: write offsets + dinv + zero fill ------------------
__global__ void k_writeoff(int N) {
    __shared__ int warpsum[32];
    __shared__ int warpexcl[32];
    int t = threadIdx.x, lane = t & 31, w = t >> 5;
    int i = blockIdx.x * SCAN_B + t;
    int c = (i < N) ? d_cnt[i] : 0;
    int x = c;
    #pragma unroll
    for (int o = 1; o < 32; o <<= 1) {
        int u = __shfl_up_sync(0xFFFFFFFFu, x, o);
        if (lane >= o) x += u;
    }
    if (lane == 31) warpsum[w] = x;
    __syncthreads();
    if (t < 32) {
        int orig = warpsum[t];
        int y = orig;
        #pragma unroll
        for (int o = 1; o < 32; o <<= 1) {
            int u = __shfl_up_sync(0xFFFFFFFFu, y, o);
            if (t >= o) y += u;
        }
        warpexcl[t] = y - orig;                      // exclusive, safe index
    }
    __syncthreads();
    if (i < N) {
        int pre = (x - c) + warpexcl[w] + d_bsum[blockIdx.x];
        d_off[i]  = pre;
        d_fill[i] = 0;
        d_dinv[i] = rsqrtf((float)c + 1.0f);         // +1 = self loop
    }
}

// ---------------- CSR fill --------------------------------------------------
__global__ void k_fill(const int* __restrict__ ei, int E) {
    int e = blockIdx.x * blockDim.x + threadIdx.x;
    if (e >= E) return;
    int r = ei[e];                         // source
    int c = ei[E + e];                     // target
    int p = d_off[c] + atomicAdd(&d_fill[c], 1);
    d_src[p] = r;
}

// ---------------- GEMM1: g1 = dinv * (x @ W1) -------------------------------
// block = 256 threads, 32 rows/block; 100000 = 32 * 3125.
__global__ void k_gemm1(const float* __restrict__ x, const float* __restrict__ W1) {
    __shared__ float xs[32 * 129];
    __shared__ float ws[F_IN * F_HID];
    int tid = threadIdx.x;
    int row0 = blockIdx.x * 32;

    for (int i = tid; i < F_IN * F_HID; i += 256) ws[i] = W1[i];
    for (int i = tid; i < 32 * F_IN; i += 256) {
        int r = i >> 7, k = i & 127;
        xs[r * 129 + k] = x[(row0 + r) * F_IN + k];
    }
    __syncthreads();

    #pragma unroll
    for (int it = 0; it < 2; it++) {
        int id = tid + it * 256;            // 512 items: 32 rows x 16 outs
        int r = id >> 4, j = id & 15;
        float acc = 0.f;
        #pragma unroll
        for (int k = 0; k < F_IN; k++)
            acc += xs[r * 129 + k] * ws[k * F_HID + j];
        int node = row0 + r;
        d_g1[node * F_HID + j] = acc * d_dinv[node];
    }
}

// ---------------- layer1 aggregate + ReLU + GEMM2 (warp per node) ----------
// Tail-free: every strip keeps 8 outstanding gathers; OOB lanes clamp the
// index (safe: e > s inside the loop) and predicate the accumulate.
__global__ void __launch_bounds__(256) k_agg1(const float* __restrict__ W2,
                                              const float* __restrict__ b1) {
    __shared__ float ws[F_HID * F_OUT];
    __shared__ float bs[F_HID];
    int tid = threadIdx.x;
    for (int i = tid; i < F_HID * F_OUT; i += 256) ws[i] = W2[i];
    if (tid < F_HID) bs[tid] = b1[tid];
    __syncthreads();

    int node = (blockIdx.x * 256 + tid) >> 5;     // exactly N_NODES warps
    int lane = tid & 31;
    int f = lane & 15;
    int half = lane >> 4;
    int s = d_off[node], e = d_off[node + 1];
    int last = e - 1;

    float a0 = 0.f, a1 = 0.f, a2 = 0.f, a3 = 0.f;
    float a4 = 0.f, a5 = 0.f, a6 = 0.f, a7 = 0.f;
    for (int i = s + half; i < e; i += 16) {       // 8 strided slots per half
        int j0 = i,      j1 = i + 2,  j2 = i + 4,  j3 = i + 6;
        int j4 = i + 8,  j5 = i + 10, j6 = i + 12, j7 = i + 14;
        int s0 = d_src[min(j0, last)], s1 = d_src[min(j1, last)];
        int s2 = d_src[min(j2, last)], s3 = d_src[min(j3, last)];
        int s4 = d_src[min(j4, last)], s5 = d_src[min(j5, last)];
        int s6 = d_src[min(j6, last)], s7 = d_src[min(j7, last)];
        float v0 = d_g1[s0 * F_HID + f], v1 = d_g1[s1 * F_HID + f];
        float v2 = d_g1[s2 * F_HID + f], v3 = d_g1[s3 * F_HID + f];
        float v4 = d_g1[s4 * F_HID + f], v5 = d_g1[s5 * F_HID + f];
        float v6 = d_g1[s6 * F_HID + f], v7 = d_g1[s7 * F_HID + f];
        if (j1 < e) { a0 += v0; a1 += v1; }
        else if (j0 < e) a0 += v0;
        if (j3 < e) { a2 += v2; a3 += v3; }
        else if (j2 < e) a2 += v2;
        if (j5 < e) { a4 += v4; a5 += v5; }
        else if (j4 < e) a4 += v4;
        if (j7 < e) { a6 += v6; a7 += v7; }
        else if (j6 < e) a6 += v6;
    }

    float acc = ((a0 + a1) + (a2 + a3)) + ((a4 + a5) + (a6 + a7));
    acc += __shfl_xor_sync(0xFFFFFFFFu, acc, 16);  // combine halves

    float dv = d_dinv[node];
    float h = fmaxf((acc + d_g1[node * F_HID + f]) * dv + bs[f], 0.f);

    // GEMM2 across the warp: lane j computes output feature j
    float o2 = 0.f;
    #pragma unroll
    for (int k = 0; k < F_HID; k++) {
        float hk = __shfl_sync(0xFFFFFFFFu, h, k);
        o2 += hk * ws[k * F_OUT + lane];
    }
    d_g2[node * F_OUT + lane] = o2 * dv;
}

// ---------------- layer2 aggregate + bias + log_softmax (warp per node) ----
__global__ void __launch_bounds__(256) k_agg2(const float* __restrict__ b2,
                                              float* __restrict__ out) {
    int tid = threadIdx.x;
    int node = (blockIdx.x * 256 + tid) >> 5;
    int lane = tid & 31;
    int s = d_off[node], e = d_off[node + 1];
    int last = e - 1;

    float a0 = 0.f, a1 = 0.f, a2 = 0.f, a3 = 0.f;
    float a4 = 0.f, a5 = 0.f, a6 = 0.f, a7 = 0.f;
    for (int i = s; i < e; i += 8) {               // tail-free 8-deep strips
        int j1 = i + 1, j2 = i + 2, j3 = i + 3;
        int j4 = i + 4, j5 = i + 5, j6 = i + 6, j7 = i + 7;
        int s0 = d_src[i],             s1 = d_src[min(j1, last)];
        int s2 = d_src[min(j2, last)], s3 = d_src[min(j3, last)];
        int s4 = d_src[min(j4, last)], s5 = d_src[min(j5, last)];
        int s6 = d_src[min(j6, last)], s7 = d_src[min(j7, last)];
        float v0 = d_g2[s0 * F_OUT + lane], v1 = d_g2[s1 * F_OUT + lane];
        float v2 = d_g2[s2 * F_OUT + lane], v3 = d_g2[s3 * F_OUT + lane];
        float v4 = d_g2[s4 * F_OUT + lane], v5 = d_g2[s5 * F_OUT + lane];
        float v6 = d_g2[s6 * F_OUT + lane], v7 = d_g2[s7 * F_OUT + lane];
        a0 += v0;
        if (j1 < e) a1 += v1;
        if (j2 < e) a2 += v2;
        if (j3 < e) a3 += v3;
        if (j4 < e) a4 += v4;
        if (j5 < e) a5 += v5;
        if (j6 < e) a6 += v6;
        if (j7 < e) a7 += v7;
    }

    float v = (((a0 + a1) + (a2 + a3)) + ((a4 + a5) + (a6 + a7))
               + d_g2[node * F_OUT + lane]) * d_dinv[node] + b2[lane];

    float m = v;
    #pragma unroll
    for (int o = 16; o; o >>= 1) m = fmaxf(m, __shfl_xor_sync(0xFFFFFFFFu, m, o));
    float ex = expf(v - m);
    float sum = ex;
    #pragma unroll
    for (int o = 16; o; o >>= 1) sum += __shfl_xor_sync(0xFFFFFFFFu, sum, o);
    out[node * F_OUT + lane] = v - m - logf(sum);
}

// ---------------- launcher --------------------------------------------------
extern "C" void kernel_launch(void* const* d_in, const int* in_sizes, int n_in,
                              void* d_out, int out_size) {
    const float* x  = (const float*)d_in[0];       // [N, 128] f32
    const int*   ei = (const int*)d_in[1];         // [2, E] int32
    const float* W1 = (const float*)d_in[2];       // [128, 16]
    const float* b1 = (const float*)d_in[3];       // [16]
    const float* W2 = (const float*)d_in[4];       // [16, 32]
    const float* b2 = (const float*)d_in[5];       // [32]
    float* out = (float*)d_out;

    int N = in_sizes[0] / F_IN;     // 100000
    int E = in_sizes[1] / 2;        // 3200000
    int nb = (N + SCAN_B - 1) / SCAN_B;            // 98

    k_zero    <<<(N + 255) / 256, 256>>>(N);
    k_count   <<<(E + 255) / 256, 256>>>(ei, E);
    k_blocksum<<<nb, SCAN_B>>>(N);
    k_scanb   <<<1, 32>>>(nb, N);
    k_writeoff<<<nb, SCAN_B>>>(N);
    k_fill    <<<(E + 255) / 256, 256>>>(ei, E);
    k_gemm1   <<<N / 32, 256>>>(x, W1);
    k_agg1    <<<(N * 32) / 256, 256>>>(W2, b1);   // 1 warp per node
    k_agg2    <<<(N * 32) / 256, 256>>>(b2, out);
}

// round 9
// speedup vs baseline: 1.0842x; 1.0842x over previous
#include <cuda_runtime.h>
#include <cuda_bf16.h>
#include <cstdint>

#define N_NODES 100000
#define N_EDGES 3200000
#define F_IN 128
#define F_HID 16
#define F_OUT 32
#define SCAN_B 1024
#define NB_SCAN ((N_NODES + SCAN_B - 1) / SCAN_B)   // 98

// ---------------- scratch (device globals; no allocation allowed) ----------
__device__ int   d_cnt[N_NODES];
__device__ int   d_fill[N_NODES];
__device__ int   d_off[N_NODES + 1];
__device__ int   d_bsum[NB_SCAN];
__device__ int   d_src[N_EDGES];
__device__ float d_dinv[N_NODES];
__device__ float d_g1[N_NODES * F_HID];    // dinv[i] * (x W1)[i]
__device__ float d_g2[N_NODES * F_OUT];    // dinv[i] * (h W2)[i]

// ---------------- kernel: zero counts ---------------------------------------
__global__ void k_zero(int n) {
    int i = blockIdx.x * blockDim.x + threadIdx.x;
    if (i < n) d_cnt[i] = 0;
}

// ---------------- kernel: in-degree count ----------------------------------
__global__ void k_count(const int* __restrict__ ei, int E) {
    int e = blockIdx.x * blockDim.x + threadIdx.x;
    if (e >= E) return;
    atomicAdd(&d_cnt[ei[E + e]], 1);       // edge_index[1][e] (target)
}

// ---------------- scan A: per-block sums (98 blocks x 1024) -----------------
__global__ void k_blocksum(int N) {
    __shared__ int ws[32];
    int t = threadIdx.x, lane = t & 31, w = t >> 5;
    int i = blockIdx.x * SCAN_B + t;
    int s = (i < N) ? d_cnt[i] : 0;
    #pragma unroll
    for (int o = 16; o; o >>= 1) s += __shfl_xor_sync(0xFFFFFFFFu, s, o);
    if (lane == 0) ws[w] = s;
    __syncthreads();
    if (t < 32) {
        int v = ws[t];
        #pragma unroll
        for (int o = 16; o; o >>= 1) v += __shfl_xor_sync(0xFFFFFFFFu, v, o);
        if (t == 0) d_bsum[blockIdx.x] = v;
    }
}

// ---------------- scan B: exclusive scan of 98 block sums (1 warp) ----------
__global__ void k_scanb(int nb, int N) {
    int lane = threadIdx.x;
    int carry = 0;
    for (int base = 0; base < nb; base += 32) {
        int idx = base + lane;
        int v = (idx < nb) ? d_bsum[idx] : 0;
        int x = v;
        #pragma unroll
        for (int o = 1; o < 32; o <<= 1) {
            int u = __shfl_up_sync(0xFFFFFFFFu, x, o);
            if (lane >= o) x += u;
        }
        if (idx < nb) d_bsum[idx] = carry + x - v;   // exclusive
        carry += __shfl_sync(0xFFFFFFFFu, x, 31);
    }
    if (lane == 0) d_off[N] = carry;                 // == E
}

// ---------------- scan C: write offsets + dinv + zero fill ------------------
__global__ void k_writeoff(int N) {
    __shared__ int warpsum[32];
    __shared__ int warpexcl[32];
    int t = threadIdx.x, lane = t & 31, w = t >> 5;
    int i = blockIdx.x * SCAN_B + t;
    int c = (i < N) ? d_cnt[i] : 0;
    int x = c;
    #pragma unroll
    for (int o = 1; o < 32; o <<= 1) {
        int u = __shfl_up_sync(0xFFFFFFFFu, x, o);
        if (lane >= o) x += u;
    }
    if (lane == 31) warpsum[w] = x;
    __syncthreads();
    if (t < 32) {
        int orig = warpsum[t];
        int y = orig;
        #pragma unroll
        for (int o = 1; o < 32; o <<= 1) {
            int u = __shfl_up_sync(0xFFFFFFFFu, y, o);
            if (t >= o) y += u;
        }
        warpexcl[t] = y - orig;
    }
    __syncthreads();
    if (i < N) {
        int pre = (x - c) + warpexcl[w] + d_bsum[blockIdx.x];
        d_off[i]  = pre;
        d_fill[i] = 0;
        d_dinv[i] = rsqrtf((float)c + 1.0f);         // +1 = self loop
    }
}

// ---------------- CSR fill --------------------------------------------------
__global__ void k_fill(const int* __restrict__ ei, int E) {
    int e = blockIdx.x * blockDim.x + threadIdx.x;
    if (e >= E) return;
    int r = ei[e];
    int c = ei[E + e];
    int p = d_off[c] + atomicAdd(&d_fill[c], 1);
    d_src[p] = r;
}

// ---------------- GEMM1: g1 = dinv * (x @ W1) -------------------------------
__global__ void k_gemm1(const float* __restrict__ x, const float* __restrict__ W1) {
    __shared__ float xs[32 * 129];
    __shared__ float ws[F_IN * F_HID];
    int tid = threadIdx.x;
    int row0 = blockIdx.x * 32;

    for (int i = tid; i < F_IN * F_HID; i += 256) ws[i] = W1[i];
    for (int i = tid; i < 32 * F_IN; i += 256) {
        int r = i >> 7, k = i & 127;
        xs[r * 129 + k] = x[(row0 + r) * F_IN + k];
    }
    __syncthreads();

    #pragma unroll
    for (int it = 0; it < 2; it++) {
        int id = tid + it * 256;
        int r = id >> 4, j = id & 15;
        float acc = 0.f;
        #pragma unroll
        for (int k = 0; k < F_IN; k++)
            acc += xs[r * 129 + k] * ws[k * F_HID + j];
        int node = row0 + r;
        d_g1[node * F_HID + j] = acc * d_dinv[node];
    }
}

// ---------------- layer1 agg (float4 lanes) + ReLU + GEMM2 ------------------
// lane = (g, c): g = lane>>2 (edge slot 0..7), c = lane&3 (feature quad).
// Per strip of 8 edges: 1 index LDG + 1 LDG.128 per lane.
__global__ void __launch_bounds__(256) k_agg1(const float* __restrict__ W2,
                                              const float* __restrict__ b1) {
    __shared__ float ws[F_HID * F_OUT];
    __shared__ float bs[F_HID];
    int tid = threadIdx.x;
    for (int i = tid; i < F_HID * F_OUT; i += 256) ws[i] = W2[i];
    if (tid < F_HID) bs[tid] = b1[tid];
    __syncthreads();

    int node = (blockIdx.x * 256 + tid) >> 5;
    int lane = tid & 31;
    int g = lane >> 2, c = lane & 3;
    int s = d_off[node], e = d_off[node + 1];
    int last = e - 1;

    float4 acc = make_float4(0.f, 0.f, 0.f, 0.f);
    for (int i = s; i < e; i += 8) {
        int j = i + g;
        int src = d_src[min(j, last)];
        float4 v = *reinterpret_cast<const float4*>(&d_g1[src * F_HID + c * 4]);
        if (j < e) { acc.x += v.x; acc.y += v.y; acc.z += v.z; acc.w += v.w; }
    }
    // combine the 8 edge slots (xor over g bits: 4, 8, 16)
    #pragma unroll
    for (int o = 4; o <= 16; o <<= 1) {
        acc.x += __shfl_xor_sync(0xFFFFFFFFu, acc.x, o);
        acc.y += __shfl_xor_sync(0xFFFFFFFFu, acc.y, o);
        acc.z += __shfl_xor_sync(0xFFFFFFFFu, acc.z, o);
        acc.w += __shfl_xor_sync(0xFFFFFFFFu, acc.w, o);
    }

    float dv = d_dinv[node];
    float4 sv = *reinterpret_cast<const float4*>(&d_g1[node * F_HID + c * 4]);
    float h0 = fmaxf((acc.x + sv.x) * dv + bs[c * 4 + 0], 0.f);
    float h1 = fmaxf((acc.y + sv.y) * dv + bs[c * 4 + 1], 0.f);
    float h2 = fmaxf((acc.z + sv.z) * dv + bs[c * 4 + 2], 0.f);
    float h3 = fmaxf((acc.w + sv.w) * dv + bs[c * 4 + 3], 0.f);

    // GEMM2: lane j computes output feature j; h[k] lives in lane k>>2, comp k&3
    float o2 = 0.f;
    #pragma unroll
    for (int q = 0; q < 4; q++) {
        float hq = (q == 0) ? h0 : (q == 1) ? h1 : (q == 2) ? h2 : h3;
        #pragma unroll
        for (int cc = 0; cc < 4; cc++) {
            float hk = __shfl_sync(0xFFFFFFFFu, hq, cc);   // lane cc has c==cc
            o2 += hk * ws[(cc * 4 + q) * F_OUT + lane];
        }
    }
    d_g2[node * F_OUT + lane] = o2 * dv;
}

// ---------------- layer2 agg (float4 lanes) + bias + log_softmax ------------
// lane = (g, c): g = lane>>3 (edge slot 0..3), c = lane&7 (feature quad).
// Two strips in flight: 8 edges per iteration, 2 LDG.128 per lane.
__global__ void __launch_bounds__(256) k_agg2(const float* __restrict__ b2,
                                              float* __restrict__ out) {
    int tid = threadIdx.x;
    int node = (blockIdx.x * 256 + tid) >> 5;
    int lane = tid & 31;
    int g = lane >> 3, c = lane & 7;
    int s = d_off[node], e = d_off[node + 1];
    int last = e - 1;

    float4 acc0 = make_float4(0.f, 0.f, 0.f, 0.f);
    float4 acc1 = make_float4(0.f, 0.f, 0.f, 0.f);
    for (int i = s; i < e; i += 8) {
        int j0 = i + g, j1 = i + 4 + g;
        int s0 = d_src[min(j0, last)];
        int s1 = d_src[min(j1, last)];
        float4 v0 = *reinterpret_cast<const float4*>(&d_g2[s0 * F_OUT + c * 4]);
        float4 v1 = *reinterpret_cast<const float4*>(&d_g2[s1 * F_OUT + c * 4]);
        if (j0 < e) { acc0.x += v0.x; acc0.y += v0.y; acc0.z += v0.z; acc0.w += v0.w; }
        if (j1 < e) { acc1.x += v1.x; acc1.y += v1.y; acc1.z += v1.z; acc1.w += v1.w; }
    }
    acc0.x += acc1.x; acc0.y += acc1.y; acc0.z += acc1.z; acc0.w += acc1.w;
    // combine the 4 edge slots (xor over g bits: 8, 16)
    #pragma unroll
    for (int o = 8; o <= 16; o <<= 1) {
        acc0.x += __shfl_xor_sync(0xFFFFFFFFu, acc0.x, o);
        acc0.y += __shfl_xor_sync(0xFFFFFFFFu, acc0.y, o);
        acc0.z += __shfl_xor_sync(0xFFFFFFFFu, acc0.z, o);
        acc0.w += __shfl_xor_sync(0xFFFFFFFFu, acc0.w, o);
    }

    float dv = d_dinv[node];
    float4 sv = *reinterpret_cast<const float4*>(&d_g2[node * F_OUT + c * 4]);
    float v0 = (acc0.x + sv.x) * dv + b2[c * 4 + 0];
    float v1 = (acc0.y + sv.y) * dv + b2[c * 4 + 1];
    float v2 = (acc0.z + sv.z) * dv + b2[c * 4 + 2];
    float v3 = (acc0.w + sv.w) * dv + b2[c * 4 + 3];

    // max over 32 features: per-lane max of quad, then xor over c bits (1,2,4)
    float m = fmaxf(fmaxf(v0, v1), fmaxf(v2, v3));
    #pragma unroll
    for (int o = 1; o <= 4; o <<= 1) m = fmaxf(m, __shfl_xor_sync(0xFFFFFFFFu, m, o));
    float sq = expf(v0 - m) + expf(v1 - m) + expf(v2 - m) + expf(v3 - m);
    #pragma unroll
    for (int o = 1; o <= 4; o <<= 1) sq += __shfl_xor_sync(0xFFFFFFFFu, sq, o);
    float ls = m + logf(sq);

    if (g == 0) {   // lanes 0..7 write the full 32-float row as 8 float4s
        float4 r = make_float4(v0 - ls, v1 - ls, v2 - ls, v3 - ls);
        *reinterpret_cast<float4*>(&out[node * F_OUT + c * 4]) = r;
    }
}

// ---------------- launcher --------------------------------------------------
extern "C" void kernel_launch(void* const* d_in, const int* in_sizes, int n_in,
                              void* d_out, int out_size) {
    const float* x  = (const float*)d_in[0];       // [N, 128] f32
    const int*   ei = (const int*)d_in[1];         // [2, E] int32
    const float* W1 = (const float*)d_in[2];       // [128, 16]
    const float* b1 = (const float*)d_in[3];       // [16]
    const float* W2 = (const float*)d_in[4];       // [16, 32]
    const float* b2 = (const float*)d_in[5];       // [32]
    float* out = (float*)d_out;

    int N = in_sizes[0] / F_IN;     // 100000
    int E = in_sizes[1] / 2;        // 3200000
    int nb = (N + SCAN_B - 1) / SCAN_B;            // 98

    k_zero    <<<(N + 255) / 256, 256>>>(N);
    k_count   <<<(E + 255) / 256, 256>>>(ei, E);
    k_blocksum<<<nb, SCAN_B>>>(N);
    k_scanb   <<<1, 32>>>(nb, N);
    k_writeoff<<<nb, SCAN_B>>>(N);
    k_fill    <<<(E + 255) / 256, 256>>>(ei, E);
    k_gemm1   <<<N / 32, 256>>>(x, W1);
    k_agg1    <<<(N * 32) / 256, 256>>>(W2, b1);   // 1 warp per node
    k_agg2    <<<(N * 32) / 256, 256>>>(b2, out);
}

// round 10
// speedup vs baseline: 1.0954x; 1.0104x over previous
#include <cuda_runtime.h>
#include <cuda_bf16.h>
#include <cstdint>

#define N_NODES 100000
#define N_EDGES 3200000
#define F_IN 128
#define F_HID 16
#define F_OUT 32
#define SCAN_B 1024
#define NB_SCAN ((N_NODES + SCAN_B - 1) / SCAN_B)   // 98

// ---------------- scratch (device globals; no allocation allowed) ----------
// d_cnt: zero-initialized at module load; k_writeoff re-zeroes it each run.
__device__ int   d_cnt[N_NODES];
__device__ int   d_fill[N_NODES];
__device__ int   d_off[N_NODES + 1];
__device__ int   d_bsum[NB_SCAN];
__device__ int   d_src[N_EDGES];
__device__ float d_dinv[N_NODES];
__device__ float d_g1[N_NODES * F_HID];    // dinv[i] * (x W1)[i]
__device__ float d_g2[N_NODES * F_OUT];    // dinv[i] * (h W2)[i]

// ---------------- kernel: in-degree count (4 edges/thread, int4) -----------
__global__ void k_count(const int* __restrict__ ei, int E) {
    int t = blockIdx.x * blockDim.x + threadIdx.x;
    int e = t * 4;
    if (e + 3 < E) {
        int4 c = *reinterpret_cast<const int4*>(&ei[E + e]);
        atomicAdd(&d_cnt[c.x], 1);
        atomicAdd(&d_cnt[c.y], 1);
        atomicAdd(&d_cnt[c.z], 1);
        atomicAdd(&d_cnt[c.w], 1);
    } else {
        for (int k = e; k < E; k++) atomicAdd(&d_cnt[ei[E + k]], 1);
    }
}

// ---------------- scan A: per-block sums (98 blocks x 1024) -----------------
__global__ void k_blocksum(int N) {
    __shared__ int ws[32];
    int t = threadIdx.x, lane = t & 31, w = t >> 5;
    int i = blockIdx.x * SCAN_B + t;
    int s = (i < N) ? d_cnt[i] : 0;
    #pragma unroll
    for (int o = 16; o; o >>= 1) s += __shfl_xor_sync(0xFFFFFFFFu, s, o);
    if (lane == 0) ws[w] = s;
    __syncthreads();
    if (t < 32) {
        int v = ws[t];
        #pragma unroll
        for (int o = 16; o; o >>= 1) v += __shfl_xor_sync(0xFFFFFFFFu, v, o);
        if (t == 0) d_bsum[blockIdx.x] = v;
    }
}

// ---------------- scan B: exclusive scan of 98 block sums (1 warp) ----------
__global__ void k_scanb(int nb, int N) {
    int lane = threadIdx.x;
    int carry = 0;
    for (int base = 0; base < nb; base += 32) {
        int idx = base + lane;
        int v = (idx < nb) ? d_bsum[idx] : 0;
        int x = v;
        #pragma unroll
        for (int o = 1; o < 32; o <<= 1) {
            int u = __shfl_up_sync(0xFFFFFFFFu, x, o);
            if (lane >= o) x += u;
        }
        if (idx < nb) d_bsum[idx] = carry + x - v;   // exclusive
        carry += __shfl_sync(0xFFFFFFFFu, x, 31);
    }
    if (lane == 0) d_off[N] = carry;                 // == E
}

// ---------------- scan C: write offsets + dinv; zero cnt & fill -------------
__global__ void k_writeoff(int N) {
    __shared__ int warpsum[32];
    __shared__ int warpexcl[32];
    int t = threadIdx.x, lane = t & 31, w = t >> 5;
    int i = blockIdx.x * SCAN_B + t;
    int c = (i < N) ? d_cnt[i] : 0;
    int x = c;
    #pragma unroll
    for (int o = 1; o < 32; o <<= 1) {
        int u = __shfl_up_sync(0xFFFFFFFFu, x, o);
        if (lane >= o) x += u;
    }
    if (lane == 31) warpsum[w] = x;
    __syncthreads();
    if (t < 32) {
        int orig = warpsum[t];
        int y = orig;
        #pragma unroll
        for (int o = 1; o < 32; o <<= 1) {
            int u = __shfl_up_sync(0xFFFFFFFFu, y, o);
            if (t >= o) y += u;
        }
        warpexcl[t] = y - orig;
    }
    __syncthreads();
    if (i < N) {
        int pre = (x - c) + warpexcl[w] + d_bsum[blockIdx.x];
        d_off[i]  = pre;
        d_fill[i] = 0;
        d_cnt[i]  = 0;                               // ready for next replay
        d_dinv[i] = rsqrtf((float)c + 1.0f);         // +1 = self loop
    }
}

// ---------------- CSR fill (4 edges/thread, int4) ---------------------------
__global__ void k_fill(const int* __restrict__ ei, int E) {
    int t = blockIdx.x * blockDim.x + threadIdx.x;
    int e = t * 4;
    if (e + 3 < E) {
        int4 r = *reinterpret_cast<const int4*>(&ei[e]);
        int4 c = *reinterpret_cast<const int4*>(&ei[E + e]);
        d_src[d_off[c.x] + atomicAdd(&d_fill[c.x], 1)] = r.x;
        d_src[d_off[c.y] + atomicAdd(&d_fill[c.y], 1)] = r.y;
        d_src[d_off[c.z] + atomicAdd(&d_fill[c.z], 1)] = r.z;
        d_src[d_off[c.w] + atomicAdd(&d_fill[c.w], 1)] = r.w;
    } else {
        for (int k = e; k < E; k++) {
            int c = ei[E + k];
            d_src[d_off[c] + atomicAdd(&d_fill[c], 1)] = ei[k];
        }
    }
}

// ---------------- GEMM1: g1 = dinv * (x @ W1) -------------------------------
__global__ void k_gemm1(const float* __restrict__ x, const float* __restrict__ W1) {
    __shared__ float xs[32 * 129];
    __shared__ float ws[F_IN * F_HID];
    int tid = threadIdx.x;
    int row0 = blockIdx.x * 32;

    for (int i = tid; i < F_IN * F_HID; i += 256) ws[i] = W1[i];
    for (int i = tid; i < 32 * F_IN; i += 256) {
        int r = i >> 7, k = i & 127;
        xs[r * 129 + k] = x[(row0 + r) * F_IN + k];
    }
    __syncthreads();

    #pragma unroll
    for (int it = 0; it < 2; it++) {
        int id = tid + it * 256;
        int r = id >> 4, j = id & 15;
        float acc = 0.f;
        #pragma unroll
        for (int k = 0; k < F_IN; k++)
            acc += xs[r * 129 + k] * ws[k * F_HID + j];
        int node = row0 + r;
        d_g1[node * F_HID + j] = acc * d_dinv[node];
    }
}

// ---------------- layer1 agg (float4 lanes, pipelined) + ReLU + GEMM2 -------
// lane = (g, c): g = lane>>2 (edge slot 0..7), c = lane&3 (feature quad).
// Next strip's indices are prefetched before consuming current gathers.
__global__ void __launch_bounds__(256) k_agg1(const float* __restrict__ W2,
                                              const float* __restrict__ b1) {
    __shared__ float ws[F_HID * F_OUT];
    __shared__ float bs[F_HID];
    int tid = threadIdx.x;
    for (int i = tid; i < F_HID * F_OUT; i += 256) ws[i] = W2[i];
    if (tid < F_HID) bs[tid] = b1[tid];
    __syncthreads();

    int node = (blockIdx.x * 256 + tid) >> 5;
    int lane = tid & 31;
    int g = lane >> 2, c = lane & 3;
    int s = d_off[node], e = d_off[node + 1];
    int last = e - 1;

    float4 acc = make_float4(0.f, 0.f, 0.f, 0.f);
    int i = s;
    int idx = d_src[min(i + g, last)];             // prime the pipeline
    for (; i < e; ) {
        int inext = i + 8;
        int idx_n = d_src[min(inext + g, last)];   // prefetch next strip
        float4 v = *reinterpret_cast<const float4*>(&d_g1[idx * F_HID + c * 4]);
        if (i + g < e) { acc.x += v.x; acc.y += v.y; acc.z += v.z; acc.w += v.w; }
        i = inext;
        idx = idx_n;
    }
    // combine the 8 edge slots (xor over g bits: 4, 8, 16)
    #pragma unroll
    for (int o = 4; o <= 16; o <<= 1) {
        acc.x += __shfl_xor_sync(0xFFFFFFFFu, acc.x, o);
        acc.y += __shfl_xor_sync(0xFFFFFFFFu, acc.y, o);
        acc.z += __shfl_xor_sync(0xFFFFFFFFu, acc.z, o);
        acc.w += __shfl_xor_sync(0xFFFFFFFFu, acc.w, o);
    }

    float dv = d_dinv[node];
    float4 sv = *reinterpret_cast<const float4*>(&d_g1[node * F_HID + c * 4]);
    float h0 = fmaxf((acc.x + sv.x) * dv + bs[c * 4 + 0], 0.f);
    float h1 = fmaxf((acc.y + sv.y) * dv + bs[c * 4 + 1], 0.f);
    float h2 = fmaxf((acc.z + sv.z) * dv + bs[c * 4 + 2], 0.f);
    float h3 = fmaxf((acc.w + sv.w) * dv + bs[c * 4 + 3], 0.f);

    // GEMM2: lane j computes output feature j; h[k] lives in lane k>>2, comp k&3
    float o2 = 0.f;
    #pragma unroll
    for (int q = 0; q < 4; q++) {
        float hq = (q == 0) ? h0 : (q == 1) ? h1 : (q == 2) ? h2 : h3;
        #pragma unroll
        for (int cc = 0; cc < 4; cc++) {
            float hk = __shfl_sync(0xFFFFFFFFu, hq, cc);   // lane cc has c==cc
            o2 += hk * ws[(cc * 4 + q) * F_OUT + lane];
        }
    }
    d_g2[node * F_OUT + lane] = o2 * dv;
}

// ---------------- layer2 agg (float4 lanes, pipelined) + log_softmax --------
// lane = (g, c): g = lane>>3 (edge slot 0..3), c = lane&7 (feature quad).
// 8 edges per strip (two 4-edge groups); next strip's indices prefetched.
__global__ void __launch_bounds__(256) k_agg2(const float* __restrict__ b2,
                                              float* __restrict__ out) {
    int tid = threadIdx.x;
    int node = (blockIdx.x * 256 + tid) >> 5;
    int lane = tid & 31;
    int g = lane >> 3, c = lane & 7;
    int s = d_off[node], e = d_off[node + 1];
    int last = e - 1;

    float4 acc0 = make_float4(0.f, 0.f, 0.f, 0.f);
    float4 acc1 = make_float4(0.f, 0.f, 0.f, 0.f);
    int i = s;
    int ia = d_src[min(i + g, last)];
    int ib = d_src[min(i + 4 + g, last)];
    for (; i < e; ) {
        int inext = i + 8;
        int ia_n = d_src[min(inext + g, last)];        // prefetch next strip
        int ib_n = d_src[min(inext + 4 + g, last)];
        float4 v0 = *reinterpret_cast<const float4*>(&d_g2[ia * F_OUT + c * 4]);
        float4 v1 = *reinterpret_cast<const float4*>(&d_g2[ib * F_OUT + c * 4]);
        if (i + g < e)     { acc0.x += v0.x; acc0.y += v0.y; acc0.z += v0.z; acc0.w += v0.w; }
        if (i + 4 + g < e) { acc1.x += v1.x; acc1.y += v1.y; acc1.z += v1.z; acc1.w += v1.w; }
        i = inext;
        ia = ia_n; ib = ib_n;
    }
    acc0.x += acc1.x; acc0.y += acc1.y; acc0.z += acc1.z; acc0.w += acc1.w;
    // combine the 4 edge slots (xor over g bits: 8, 16)
    #pragma unroll
    for (int o = 8; o <= 16; o <<= 1) {
        acc0.x += __shfl_xor_sync(0xFFFFFFFFu, acc0.x, o);
        acc0.y += __shfl_xor_sync(0xFFFFFFFFu, acc0.y, o);
        acc0.z += __shfl_xor_sync(0xFFFFFFFFu, acc0.z, o);
        acc0.w += __shfl_xor_sync(0xFFFFFFFFu, acc0.w, o);
    }

    float dv = d_dinv[node];
    float4 sv = *reinterpret_cast<const float4*>(&d_g2[node * F_OUT + c * 4]);
    float v0 = (acc0.x + sv.x) * dv + b2[c * 4 + 0];
    float v1 = (acc0.y + sv.y) * dv + b2[c * 4 + 1];
    float v2 = (acc0.z + sv.z) * dv + b2[c * 4 + 2];
    float v3 = (acc0.w + sv.w) * dv + b2[c * 4 + 3];

    // max over 32 features: per-lane max of quad, then xor over c bits (1,2,4)
    float m = fmaxf(fmaxf(v0, v1), fmaxf(v2, v3));
    #pragma unroll
    for (int o = 1; o <= 4; o <<= 1) m = fmaxf(m, __shfl_xor_sync(0xFFFFFFFFu, m, o));
    float sq = expf(v0 - m) + expf(v1 - m) + expf(v2 - m) + expf(v3 - m);
    #pragma unroll
    for (int o = 1; o <= 4; o <<= 1) sq += __shfl_xor_sync(0xFFFFFFFFu, sq, o);
    float ls = m + logf(sq);

    if (g == 0) {   // lanes 0..7 write the full 32-float row as 8 float4s
        float4 r = make_float4(v0 - ls, v1 - ls, v2 - ls, v3 - ls);
        *reinterpret_cast<float4*>(&out[node * F_OUT + c * 4]) = r;
    }
}

// ---------------- launcher --------------------------------------------------
extern "C" void kernel_launch(void* const* d_in, const int* in_sizes, int n_in,
                              void* d_out, int out_size) {
    const float* x  = (const float*)d_in[0];       // [N, 128] f32
    const int*   ei = (const int*)d_in[1];         // [2, E] int32
    const float* W1 = (const float*)d_in[2];       // [128, 16]
    const float* b1 = (const float*)d_in[3];       // [16]
    const float* W2 = (const float*)d_in[4];       // [16, 32]
    const float* b2 = (const float*)d_in[5];       // [32]
    float* out = (float*)d_out;

    int N = in_sizes[0] / F_IN;     // 100000
    int E = in_sizes[1] / 2;        // 3200000
    int nb = (N + SCAN_B - 1) / SCAN_B;            // 98
    int E4 = (E + 3) / 4;                           // threads for 4-wide kernels

    k_count   <<<(E4 + 255) / 256, 256>>>(ei, E);
    k_blocksum<<<nb, SCAN_B>>>(N);
    k_scanb   <<<1, 32>>>(nb, N);
    k_writeoff<<<nb, SCAN_B>>>(N);
    k_fill    <<<(E4 + 255) / 256, 256>>>(ei, E);
    k_gemm1   <<<N / 32, 256>>>(x, W1);
    k_agg1    <<<(N * 32) / 256, 256>>>(W2, b1);   // 1 warp per node
    k_agg2    <<<(N * 32) / 256, 256>>>(b2, out);
}